// round 9
// baseline (speedup 1.0000x reference)
#include <cuda_runtime.h>
#include <math.h>

#define NS 4096
#define NT 4096
#define NRC 222                  // row chunks
#define NPDE (NRC * 2)           // 444 = 148 SMs x 3 blocks
#define MAXROWS 19
#define W_PDE (1.0 / (4094.0 * 4094.0))
#define W_EDGE_F ((float)(10.0 / 4096.0))

typedef unsigned long long ull;

__device__ double g_part[NPDE];
__device__ unsigned int g_count = 0;

__inline__ __device__ float warp_reduce(float v) {
    #pragma unroll
    for (int o = 16; o > 0; o >>= 1) v += __shfl_down_sync(0xffffffffu, v, o);
    return v;
}
__inline__ __device__ double warp_reduce_d(double v) {
    #pragma unroll
    for (int o = 16; o > 0; o >>= 1) v += __shfl_down_sync(0xffffffffu, v, o);
    return v;
}

// ---- packed f32x2 helpers (lane0 = low 32 bits) ----
__device__ __forceinline__ ull pk(float lo, float hi) {
    ull r; asm("mov.b64 %0, {%1, %2};" : "=l"(r) : "f"(lo), "f"(hi)); return r;
}
__device__ __forceinline__ void upk(ull v, float& lo, float& hi) {
    asm("mov.b64 {%0, %1}, %2;" : "=f"(lo), "=f"(hi) : "l"(v));
}
__device__ __forceinline__ ull padd(ull a, ull b) {
    ull r; asm("add.rn.f32x2 %0, %1, %2;" : "=l"(r) : "l"(a), "l"(b)); return r;
}
__device__ __forceinline__ ull pmul(ull a, ull b) {
    ull r; asm("mul.rn.f32x2 %0, %1, %2;" : "=l"(r) : "l"(a), "l"(b)); return r;
}
__device__ __forceinline__ ull pfma(ull a, ull b, ull c) {
    ull r; asm("fma.rn.f32x2 %0, %1, %2, %3;" : "=l"(r) : "l"(a), "l"(b), "l"(c)); return r;
}

// One stencil row, 4 elements packed as 2x f32x2.
// res = dvc*inv2dt - clamp(Vuu*A1 - Vu*A2, +-H) - A3*Vu + 2.5*v0, accumulate res^2*mask.
__device__ __forceinline__ void accum2(
    ull A1p, ull nA2p, ull nA3p, float H,
    ull vm0, ull vm1, ull vc0, ull vc1, ull vp0, ull vp1,
    float c0, float c1, float c2, float c3, float lf, float rt,
    ull neg1p, ull neg2p, ull inv2dtp, ull c25p, ull mLo, ull mHi,
    ull& acc0, ull& acc1)
{
    const ull s0   = padd(vp0, vm0);
    const ull s1   = padd(vp1, vm1);
    const ull Vuu0 = pfma(neg2p, vc0, s0);
    const ull Vuu1 = pfma(neg2p, vc1, s1);
    const ull Vu0  = pfma(vm0, neg1p, vp0);        // vp - vm
    const ull Vu1  = pfma(vm1, neg1p, vp1);
    const ull raw0 = pfma(Vuu0, A1p, pmul(Vu0, nA2p));
    const ull raw1 = pfma(Vuu1, A1p, pmul(Vu1, nA2p));
    // t-direction central diff: {c1-lf, c2-c0}, {c3-c1, rt-c2}
    const ull shA = pk(lf, c0);
    const ull mid = pk(c1, c2);
    const ull shB = pk(c3, rt);
    const ull dlo = pfma(shA, neg1p, mid);
    const ull dhi = pfma(mid, neg1p, shB);
    const ull P0 = pfma(dlo, inv2dtp, pfma(nA3p, Vu0, pmul(c25p, vc0)));
    const ull P1 = pfma(dhi, inv2dtp, pfma(nA3p, Vu1, pmul(c25p, vc1)));
    // scalar clamp (no packed fp32 min/max)
    float r0, r1, r2, r3;
    upk(raw0, r0, r1); upk(raw1, r2, r3);
    r0 = fminf(fmaxf(r0, -H), H);
    r1 = fminf(fmaxf(r1, -H), H);
    r2 = fminf(fmaxf(r2, -H), H);
    r3 = fminf(fmaxf(r3, -H), H);
    ull res0 = pfma(pk(r0, r1), neg1p, P0);
    ull res1 = pfma(pk(r2, r3), neg1p, P1);
    res0 = pmul(res0, mLo);
    res1 = pmul(res1, mHi);
    acc0 = pfma(res0, res0, acc0);
    acc1 = pfma(res1, res1, acc1);
}

__global__ void __launch_bounds__(512, 3)
loss_kernel(const float* __restrict__ V, float* __restrict__ out,
            float c1f, float c2f, float su_coef, float suu_coef, float inv2dt)
{
    const int tid  = threadIdx.x;
    const int lane = tid & 31;
    const int bid  = blockIdx.x;
    const int rc   = bid >> 1;          // row chunk 0..221
    const int cb   = bid & 1;           // column half

    __shared__ float4 cstA[MAXROWS];    // {A1, A1, -A2, -A2}
    __shared__ float4 cstB[MAXROWS];    // {-A3, -A3, H, 0}
    __shared__ float s1[16], s2[16];
    __shared__ unsigned s_old;

    // balanced rows: chunks 0..97 get 19 rows, 98..221 get 18 (total 4094)
    const int i0    = 1 + rc * 18 + min(rc, 98);
    const int nrows = 18 + (rc < 98 ? 1 : 0);

    // ---- per-row folded constants (pre-duplicated for packed use) ----
    if (tid < nrows) {
        const int   i  = i0 + tid;
        const float u  = (float)i * (1.0f / 4095.0f);
        const float L  = c2f * u + c1f * (1.0f - u);
        const float S  = 100.0f + 30.0f * (L * L * L * (1.0f / 6.0f) + L);
        const float Sn = S * (1.0f / 300.0f);
        const float Sun  = su_coef * (0.5f * L * L + 1.0f) * (1.0f / 300.0f);
        const float Suun = (suu_coef * L) * (1.0f / 300.0f);
        const float invSun  = 1.0f / Sun;
        const float invSun2 = invSun * invSun;
        const float Sn2 = Sn * Sn;
        const float A1 = 16769025.0f * Sn2 * invSun2;
        const float A2 = 2047.5f * Suun * Sn2 * invSun2 * invSun;
        const float H  = 100.0f * Sn2;
        const float A3 = 2.5f * Sn * 2047.5f * invSun;
        cstA[tid] = make_float4(A1, A1, -A2, -A2);
        cstB[tid] = make_float4(-A3, -A3, H, 0.0f);
    }

    // ---- distributed BC/TC edge losses (pre-weighted), ~19 elems/block ----
    float edge = 0.0f;
    {
        const int g = bid * MAXROWS + tid;
        if (tid < MAXROWS && g < 2 * NT) {
            if (g < NT) {
                const float t = (float)g * (1.0f / 4095.0f);
                const float target = 1.0f - (100.0f * expf(-0.05f * (1.0f - t))) * (1.0f / 300.0f);
                const float d = V[(size_t)(NS - 1) * NT + g] - target;
                edge = W_EDGE_F * (d * d);
            } else {
                const int   i2 = g - NT;
                const float u  = (float)i2 * (1.0f / 4095.0f);
                const float x  = 50.0f * (u - 0.33333334f);
                const float sp = (fmaxf(x, 0.0f) + log1pf(expf(-fabsf(x)))) * (1.0f / 50.0f);
                const float d  = V[(size_t)i2 * NT + (NT - 1)] - sp;
                const float ad = fabsf(d);
                const float h  = (ad < 0.01f) ? 0.5f * d * d : 0.01f * (ad - 0.005f);
                edge = W_EDGE_F * h;
            }
        }
    }
    __syncthreads();

    // ---- PDE residual: rolling 3-row register stencil, packed f32x2 math ----
    const int jb = (cb * 512 + tid) * 4;
    const ull neg1p   = pk(-1.0f, -1.0f);
    const ull neg2p   = pk(-2.0f, -2.0f);
    const ull inv2dtp = pk(inv2dt, inv2dt);
    const ull c25p    = pk(2.5f, 2.5f);
    const ull mLo = pk((jb == 0)    ? 0.0f : 1.0f, 1.0f);
    const ull mHi = pk(1.0f, (jb == 4092) ? 0.0f : 1.0f);
    const bool needL = (lane == 0)  && (jb != 0);
    const bool needR = (lane == 31) && (jb != 4092);
    const float* pL = V + (size_t)i0 * NT + (jb - 1);
    const float* pR = V + (size_t)i0 * NT + (jb + 4);

    const float* base = V + (size_t)(i0 - 1) * NT + jb;   // row offset 0 = i0-1

    ulonglong2 vm = *(const ulonglong2*)(base);
    ulonglong2 vc = *(const ulonglong2*)(base + NT);

    ull acc0 = 0, acc1 = 0;   // 0x0 == packed {+0.f,+0.f}
    int r = 0;
    for (; r + 2 <= nrows; r += 2) {
        const float* p = base + (size_t)(r + 2) * NT;
        const ulonglong2 p0 = *(const ulonglong2*)(p);
        const ulonglong2 p1 = *(const ulonglong2*)(p + NT / 2);   // ull units

        // row r (center = vc)
        {
            float c0, c1, c2, c3;
            upk(vc.x, c0, c1); upk(vc.y, c2, c3);
            float lf = __shfl_up_sync(0xffffffffu, c3, 1);
            float rt = __shfl_down_sync(0xffffffffu, c0, 1);
            if (needL) lf = __ldg(pL + (size_t)r * NT);
            if (needR) rt = __ldg(pR + (size_t)r * NT);
            const float4 ca = cstA[r];
            const float4 cb2 = cstB[r];
            accum2(pk(ca.x, ca.y), pk(ca.z, ca.w), pk(cb2.x, cb2.y), cb2.z,
                   vm.x, vm.y, vc.x, vc.y, p0.x, p0.y,
                   c0, c1, c2, c3, lf, rt,
                   neg1p, neg2p, inv2dtp, c25p, mLo, mHi, acc0, acc1);
        }
        // row r+1 (center = p0)
        {
            float c0, c1, c2, c3;
            upk(p0.x, c0, c1); upk(p0.y, c2, c3);
            float lf = __shfl_up_sync(0xffffffffu, c3, 1);
            float rt = __shfl_down_sync(0xffffffffu, c0, 1);
            if (needL) lf = __ldg(pL + (size_t)(r + 1) * NT);
            if (needR) rt = __ldg(pR + (size_t)(r + 1) * NT);
            const float4 ca = cstA[r + 1];
            const float4 cb2 = cstB[r + 1];
            accum2(pk(ca.x, ca.y), pk(ca.z, ca.w), pk(cb2.x, cb2.y), cb2.z,
                   vc.x, vc.y, p0.x, p0.y, p1.x, p1.y,
                   c0, c1, c2, c3, lf, rt,
                   neg1p, neg2p, inv2dtp, c25p, mLo, mHi, acc0, acc1);
        }
        vm = p0; vc = p1;
    }
    if (r < nrows) {
        const ulonglong2 p0 = *(const ulonglong2*)(base + (size_t)(r + 2) * NT);
        float c0, c1, c2, c3;
        upk(vc.x, c0, c1); upk(vc.y, c2, c3);
        float lf = __shfl_up_sync(0xffffffffu, c3, 1);
        float rt = __shfl_down_sync(0xffffffffu, c0, 1);
        if (needL) lf = __ldg(pL + (size_t)r * NT);
        if (needR) rt = __ldg(pR + (size_t)r * NT);
        const float4 ca = cstA[r];
        const float4 cb2 = cstB[r];
        accum2(pk(ca.x, ca.y), pk(ca.z, ca.w), pk(cb2.x, cb2.y), cb2.z,
               vm.x, vm.y, vc.x, vc.y, p0.x, p0.y,
               c0, c1, c2, c3, lf, rt,
               neg1p, neg2p, inv2dtp, c25p, mLo, mHi, acc0, acc1);
    }

    // collapse packed accumulators
    float a0, a1, a2, a3;
    upk(acc0, a0, a1); upk(acc1, a2, a3);
    float part = (a0 + a1) + (a2 + a3);

    // ---- block reduce ----
    part = warp_reduce(part);
    edge = warp_reduce(edge);
    if ((tid & 31) == 0) { s1[tid >> 5] = part; s2[tid >> 5] = edge; }
    __syncthreads();
    if (tid < 32) {
        float vpp = (tid < 16) ? s1[tid] : 0.0f;
        float vee = (tid < 16) ? s2[tid] : 0.0f;
        vpp = warp_reduce(vpp);
        vee = warp_reduce(vee);
        if (tid == 0) {
            g_part[bid] = (double)vpp * W_PDE + (double)vee;
            __threadfence();
            s_old = atomicAdd(&g_count, 1u);
        }
    }
    __syncthreads();

    // ---- last block finishes: plain sum of 444 doubles ----
    if (s_old == NPDE - 1) {
        __threadfence();
        double v = (tid < NPDE) ? g_part[tid] : 0.0;
        v = warp_reduce_d(v);
        __shared__ double sd[16];
        if ((tid & 31) == 0) sd[tid >> 5] = v;
        __syncthreads();
        if (tid < 32) {
            double t2 = (tid < 16) ? sd[tid] : 0.0;
            t2 = warp_reduce_d(t2);
            if (tid == 0) {
                out[0] = (float)t2;
                g_count = 0;   // reset for next graph replay (deterministic)
            }
        }
    }
}

static double solve_depressed_cubic(double Q) {
    const double p = 6.0;             // CHI
    const double q = 6.0 * Q;
    const double sp = sqrt(p);
    double arg = fabs(q) / (2.0 * p * sp / (3.0 * sqrt(3.0)));
    if (arg < 1.0) arg = 1.0;
    const double c = 2.0 * sp * cosh(acosh(arg) / 3.0);
    return (q >= 0.0) ? -c : c;
}

extern "C" void kernel_launch(void* const* d_in, const int* in_sizes, int n_in,
                              void* d_out, int out_size)
{
    const float* V = (const float*)d_in[0];
    float* out = (float*)d_out;

    const double C1 = solve_depressed_cubic((100.0 - 0.0) / 30.0);
    const double C2 = solve_depressed_cubic((100.0 - 300.0) / 30.0);
    const double dL = C2 - C1;
    const float c1f = (float)C1;
    const float c2f = (float)C2;
    const float su_coef  = (float)(30.0 * dL);
    const float suu_coef = (float)(30.0 * dL * dL);
    const double TAU_MAX = 0.5 * 0.2 * 0.2 * 1.0;     // 0.02
    const double DT_NORM = TAU_MAX / (double)(NT - 1);
    const float inv2dt = (float)(1.0 / (2.0 * DT_NORM));

    loss_kernel<<<NPDE, 512>>>(V, out, c1f, c2f, su_coef, suu_coef, inv2dt);
}